// round 1
// baseline (speedup 1.0000x reference)
#include <cuda_runtime.h>
#include <cuda_bf16.h>
#include <math.h>

// ---------------------------------------------------------------------------
// Problem constants (shapes fixed by the dataset; N taken from in_sizes).
//   x: [N,64], segment_ids: [N] sorted, S = B*D = 16384
//   branch A (table_forward): 64->128 relu ->32 relu -> segment_sum
//   branch B (rl):            64->128 relu ->32 relu -> segment_sum
//   then tiny per-segment heads + cost MLP + policy head -> logits[S]
// ---------------------------------------------------------------------------

#define F_IN        64
#define H0          128       // per-branch hidden
#define H0C         256       // concatenated hidden (tfc|rl)
#define H1          32        // per-branch out
#define H1C         64        // concatenated out
#define S_SEG       16384
#define TILE_R      32        // rows per tile
#define BLK_A       512       // threads, phase A
#define GRID_A      740       // 5 * 148
#define HS_STRIDE   264       // Hs row stride (256 + 8 pad, float4-aligned)

// Segment accumulator: [S][64]  cols 0..31 = tfc branch, 32..63 = rl branch
__device__ float g_segbuf[S_SEG * H1C];

// ---------------------------------------------------------------------------
// Zero kernel (segbuf must be re-zeroed on every graph replay)
// ---------------------------------------------------------------------------
__global__ void zero_kernel(int n4) {
    int i = blockIdx.x * blockDim.x + threadIdx.x;
    if (i < n4) {
        float4 z = make_float4(0.f, 0.f, 0.f, 0.f);
        reinterpret_cast<float4*>(g_segbuf)[i] = z;
    }
}

// ---------------------------------------------------------------------------
// Phase A: fused dual-branch MLP + segment reduction.
// Dynamic shared layout (floats):
//   Ws0 [64][256]      16384
//   Ws1 [128][64]       8192
//   bias0 [256]          256
//   bias1 [64]            64
//   Xs  [32][64]        2048
//   Hs  [32][264]       8448
//   Gs  [32][64]        2048
//   sid [32] (int)        32
// total = 37472 floats = 149888 bytes
// ---------------------------------------------------------------------------
#define SMEM_A_BYTES (37472 * 4)

__global__ __launch_bounds__(BLK_A, 1)
void phaseA_kernel(const float* __restrict__ x,
                   const int*   __restrict__ seg_ids,
                   const float* __restrict__ tfc0_w, const float* __restrict__ tfc0_b,
                   const float* __restrict__ tfc1_w, const float* __restrict__ tfc1_b,
                   const float* __restrict__ rl0_w,  const float* __restrict__ rl0_b,
                   const float* __restrict__ rl1_w,  const float* __restrict__ rl1_b,
                   int N)
{
    extern __shared__ float sm[];
    float* Ws0   = sm;                       // 64*256
    float* Ws1   = Ws0 + F_IN * H0C;         // 128*64
    float* bias0 = Ws1 + 2 * H0 * H1C / 2 * 2; // 128*64 floats
    // (compute offsets explicitly to avoid confusion)
    Ws1   = sm + F_IN * H0C;                          // 16384
    bias0 = Ws1 + (2 * H0) * H1C;                     // +8192 -> 24576... careful:
    // Ws1 is [128][64] = 8192 floats (K=128 per half, 64 cols)
    bias0 = sm + F_IN * H0C + 128 * H1C;              // 16384 + 8192
    float* bias1 = bias0 + H0C;                       // +256
    float* Xs    = bias1 + H1C;                       // +64
    float* Hs    = Xs + TILE_R * F_IN;                // +2048
    float* Gs    = Hs + TILE_R * HS_STRIDE;           // +8448
    int*   sid_s = (int*)(Gs + TILE_R * H1C);         // +2048

    const int t = threadIdx.x;

    // ---- stage weights (once per block) ----
    for (int i = t; i < F_IN * H0; i += BLK_A) {       // 64*128
        int k = i / H0, j = i % H0;
        Ws0[k * H0C + j]       = tfc0_w[i];
        Ws0[k * H0C + H0 + j]  = rl0_w[i];
    }
    for (int i = t; i < H0 * H1; i += BLK_A) {         // 128*32
        int k = i / H1, j = i % H1;
        Ws1[k * H1C + j]       = tfc1_w[i];
        Ws1[k * H1C + H1 + j]  = rl1_w[i];
    }
    if (t < H0) { bias0[t] = tfc0_b[t]; bias0[H0 + t] = rl0_b[t]; }
    if (t < H1) { bias1[t] = tfc1_b[t]; bias1[H1 + t] = rl1_b[t]; }
    __syncthreads();

    const int ntiles = (N + TILE_R - 1) / TILE_R;

    const int ct = t & 63;        // L0 col tile (4 cols each)
    const int rt = t >> 6;        // L0 row tile (4 rows each)
    const int j1 = t & 63;        // L1 output col
    const int rg = t >> 6;        // L1 row group (4 rows each)
    const int hbase = (j1 >= H1) ? H0 : 0;   // which half of Hs feeds this col

    for (int tile = blockIdx.x; tile < ntiles; tile += gridDim.x) {
        const int row0  = tile * TILE_R;
        const int valid = min(TILE_R, N - row0);

        // ---- stage X tile + segment ids ----
        {
            int r = t >> 4;            // 0..31
            int c = (t & 15) * 4;      // 0..60
            float4 v = make_float4(0.f, 0.f, 0.f, 0.f);
            if (r < valid)
                v = *reinterpret_cast<const float4*>(&x[(size_t)(row0 + r) * F_IN + c]);
            *reinterpret_cast<float4*>(&Xs[r * F_IN + c]) = v;
        }
        if (t < TILE_R) sid_s[t] = (t < valid) ? seg_ids[row0 + t] : 0;
        __syncthreads();

        // ---- layer 0: [32 x 64] @ [64 x 256] -> relu -> Hs ----
        {
            float acc[4][4];
            #pragma unroll
            for (int i = 0; i < 4; ++i)
                #pragma unroll
                for (int j = 0; j < 4; ++j) acc[i][j] = 0.f;

            #pragma unroll 4
            for (int k4 = 0; k4 < 16; ++k4) {
                float xr[4][4];
                #pragma unroll
                for (int i = 0; i < 4; ++i) {
                    float4 xv = *reinterpret_cast<const float4*>(
                        &Xs[(rt * 4 + i) * F_IN + k4 * 4]);
                    xr[i][0] = xv.x; xr[i][1] = xv.y; xr[i][2] = xv.z; xr[i][3] = xv.w;
                }
                #pragma unroll
                for (int kk = 0; kk < 4; ++kk) {
                    float4 wv = *reinterpret_cast<const float4*>(
                        &Ws0[(k4 * 4 + kk) * H0C + ct * 4]);
                    #pragma unroll
                    for (int i = 0; i < 4; ++i) {
                        acc[i][0] = fmaf(xr[i][kk], wv.x, acc[i][0]);
                        acc[i][1] = fmaf(xr[i][kk], wv.y, acc[i][1]);
                        acc[i][2] = fmaf(xr[i][kk], wv.z, acc[i][2]);
                        acc[i][3] = fmaf(xr[i][kk], wv.w, acc[i][3]);
                    }
                }
            }
            float4 bv = *reinterpret_cast<const float4*>(&bias0[ct * 4]);
            #pragma unroll
            for (int i = 0; i < 4; ++i) {
                float4 o;
                o.x = fmaxf(acc[i][0] + bv.x, 0.f);
                o.y = fmaxf(acc[i][1] + bv.y, 0.f);
                o.z = fmaxf(acc[i][2] + bv.z, 0.f);
                o.w = fmaxf(acc[i][3] + bv.w, 0.f);
                *reinterpret_cast<float4*>(&Hs[(rt * 4 + i) * HS_STRIDE + ct * 4]) = o;
            }
        }
        __syncthreads();

        // ---- layer 1: per half, [32 x 128] @ [128 x 32] -> relu -> Gs ----
        {
            float acc1[4] = {0.f, 0.f, 0.f, 0.f};
            #pragma unroll 8
            for (int k4 = 0; k4 < 32; ++k4) {
                float hr[4][4];
                #pragma unroll
                for (int i = 0; i < 4; ++i) {
                    float4 hv = *reinterpret_cast<const float4*>(
                        &Hs[(rg * 4 + i) * HS_STRIDE + hbase + k4 * 4]);
                    hr[i][0] = hv.x; hr[i][1] = hv.y; hr[i][2] = hv.z; hr[i][3] = hv.w;
                }
                float wk[4];
                #pragma unroll
                for (int kk = 0; kk < 4; ++kk)
                    wk[kk] = Ws1[(k4 * 4 + kk) * H1C + j1];
                #pragma unroll
                for (int i = 0; i < 4; ++i) {
                    acc1[i] = fmaf(hr[i][0], wk[0], acc1[i]);
                    acc1[i] = fmaf(hr[i][1], wk[1], acc1[i]);
                    acc1[i] = fmaf(hr[i][2], wk[2], acc1[i]);
                    acc1[i] = fmaf(hr[i][3], wk[3], acc1[i]);
                }
            }
            const float bj = bias1[j1];
            #pragma unroll
            for (int i = 0; i < 4; ++i)
                Gs[(rg * 4 + i) * H1C + j1] = fmaxf(acc1[i] + bj, 0.f);
        }
        __syncthreads();

        // ---- run-length segment reduction (seg ids are sorted) ----
        if (t < H1C) {
            float run = 0.f;
            int prev = sid_s[0];
            for (int r = 0; r < valid; ++r) {
                int sd = sid_s[r];
                if (sd != prev) {
                    atomicAdd(&g_segbuf[prev * H1C + t], run);
                    run = 0.f;
                    prev = sd;
                }
                run += Gs[r * H1C + t];
            }
            if (valid > 0) atomicAdd(&g_segbuf[prev * H1C + t], run);
        }
        __syncthreads();
    }
}

// ---------------------------------------------------------------------------
// Phase B: per-segment heads + cost MLP + policy. One warp per segment.
// ---------------------------------------------------------------------------
__global__ __launch_bounds__(256)
void phaseB_kernel(const float* __restrict__ fwd0_w, const float* __restrict__ fwd0_b,
                   const float* __restrict__ fwd1_w, const float* __restrict__ fwd1_b,
                   const float* __restrict__ com0_w, const float* __restrict__ com0_b,
                   const float* __restrict__ com1_w, const float* __restrict__ com1_b,
                   const float* __restrict__ bwd0_w, const float* __restrict__ bwd0_b,
                   const float* __restrict__ bwd1_w, const float* __restrict__ bwd1_b,
                   const float* __restrict__ cost0_w, const float* __restrict__ cost0_b,
                   const float* __restrict__ cost1_w, const float* __restrict__ cost1_b,
                   const float* __restrict__ pol_w,   const float* __restrict__ pol_b,
                   float* __restrict__ out, int S)
{
    __shared__ float s_f0[32 * 64], s_c0[32 * 64], s_b0[32 * 64];
    __shared__ float s_f0b[64], s_c0b[64], s_b0b[64];
    __shared__ float s_f1[64], s_c1[64], s_b1[64];
    __shared__ float s_k0[3 * 64], s_k0b[64];
    __shared__ float s_k1[64 * 32], s_k1b[32];
    __shared__ float s_pol[64];
    __shared__ float s_scal[4]; // f1b, c1b, b1b, polb

    const int t = threadIdx.x;
    for (int i = t; i < 32 * 64; i += 256) {
        s_f0[i] = fwd0_w[i]; s_c0[i] = com0_w[i]; s_b0[i] = bwd0_w[i];
    }
    for (int i = t; i < 64 * 32; i += 256) s_k1[i] = cost1_w[i];
    if (t < 64) {
        s_f0b[t] = fwd0_b[t]; s_c0b[t] = com0_b[t]; s_b0b[t] = bwd0_b[t];
        s_f1[t] = fwd1_w[t];  s_c1[t] = com1_w[t];  s_b1[t] = bwd1_w[t];
        s_k0b[t] = cost0_b[t]; s_pol[t] = pol_w[t];
    }
    if (t < 3 * 64 && t >= 64) s_k0[t] = cost0_w[t];
    if (t < 64) s_k0[t] = cost0_w[t];
    if (t < 32) s_k1b[t] = cost1_b[t];
    if (t == 0) {
        s_scal[0] = fwd1_b[0]; s_scal[1] = com1_b[0];
        s_scal[2] = bwd1_b[0]; s_scal[3] = pol_b[0];
    }
    __syncthreads();

    const int l = t & 31;
    const int warp = (blockIdx.x * blockDim.x + t) >> 5;
    const int nwarps = (gridDim.x * blockDim.x) >> 5;

    for (int s = warp; s < S; s += nwarps) {
        const float st = g_segbuf[s * 64 + l];        // tfc branch
        const float sr = g_segbuf[s * 64 + 32 + l];   // rl branch

        float hf0 = s_f0b[l], hf1 = s_f0b[l + 32];
        float hc0 = s_c0b[l], hc1 = s_c0b[l + 32];
        float hb0 = s_b0b[l], hb1 = s_b0b[l + 32];
        #pragma unroll
        for (int k = 0; k < 32; ++k) {
            float sk = __shfl_sync(0xffffffffu, st, k);
            hf0 = fmaf(sk, s_f0[k * 64 + l],      hf0);
            hf1 = fmaf(sk, s_f0[k * 64 + l + 32], hf1);
            hc0 = fmaf(sk, s_c0[k * 64 + l],      hc0);
            hc1 = fmaf(sk, s_c0[k * 64 + l + 32], hc1);
            hb0 = fmaf(sk, s_b0[k * 64 + l],      hb0);
            hb1 = fmaf(sk, s_b0[k * 64 + l + 32], hb1);
        }
        float vf = fmaxf(hf0, 0.f) * s_f1[l] + fmaxf(hf1, 0.f) * s_f1[l + 32];
        float vc = fmaxf(hc0, 0.f) * s_c1[l] + fmaxf(hc1, 0.f) * s_c1[l + 32];
        float vb = fmaxf(hb0, 0.f) * s_b1[l] + fmaxf(hb1, 0.f) * s_b1[l + 32];
        #pragma unroll
        for (int o = 16; o > 0; o >>= 1) {
            vf += __shfl_xor_sync(0xffffffffu, vf, o);
            vc += __shfl_xor_sync(0xffffffffu, vc, o);
            vb += __shfl_xor_sync(0xffffffffu, vb, o);
        }
        const float fwd = vf + s_scal[0];
        const float com = vc + s_scal[1];
        const float bwd = vb + s_scal[2];

        // cost MLP layer 1 (3 -> 64): lane l owns cols l and l+32
        float c1a = fmaf(fwd, s_k0[l],
                    fmaf(com, s_k0[64 + l],
                    fmaf(bwd, s_k0[128 + l], s_k0b[l])));
        float c1b = fmaf(fwd, s_k0[l + 32],
                    fmaf(com, s_k0[64 + l + 32],
                    fmaf(bwd, s_k0[128 + l + 32], s_k0b[l + 32])));
        c1a = fmaxf(c1a, 0.f);
        c1b = fmaxf(c1b, 0.f);

        // cost MLP layer 2 (64 -> 32): lane l owns output m = l
        float c2 = s_k1b[l];
        #pragma unroll
        for (int jj = 0; jj < 32; ++jj) {
            float a = __shfl_sync(0xffffffffu, c1a, jj);
            float b = __shfl_sync(0xffffffffu, c1b, jj);
            c2 = fmaf(a, s_k1[jj * 32 + l], c2);
            c2 = fmaf(b, s_k1[(jj + 32) * 32 + l], c2);
        }
        c2 = fmaxf(c2, 0.f);

        // policy: latent = [sr(32) | c2(32)]
        float v = fmaf(sr, s_pol[l], c2 * s_pol[l + 32]);
        #pragma unroll
        for (int o = 16; o > 0; o >>= 1)
            v += __shfl_xor_sync(0xffffffffu, v, o);
        if (l == 0) out[s] = v + s_scal[3];
    }
}

// ---------------------------------------------------------------------------
// Launch
// ---------------------------------------------------------------------------
extern "C" void kernel_launch(void* const* d_in, const int* in_sizes, int n_in,
                              void* d_out, int out_size)
{
    const float* x      = (const float*)d_in[0];
    const int*   sid    = (const int*)  d_in[1];
    // d_in[2] = B, d_in[3] = D (scalars, shapes are fixed -> unused)
    const float* tfc0_w = (const float*)d_in[4];
    const float* tfc0_b = (const float*)d_in[5];
    const float* tfc1_w = (const float*)d_in[6];
    const float* tfc1_b = (const float*)d_in[7];
    const float* fwd0_w = (const float*)d_in[8];
    const float* fwd0_b = (const float*)d_in[9];
    const float* fwd1_w = (const float*)d_in[10];
    const float* fwd1_b = (const float*)d_in[11];
    const float* com0_w = (const float*)d_in[12];
    const float* com0_b = (const float*)d_in[13];
    const float* com1_w = (const float*)d_in[14];
    const float* com1_b = (const float*)d_in[15];
    const float* bwd0_w = (const float*)d_in[16];
    const float* bwd0_b = (const float*)d_in[17];
    const float* bwd1_w = (const float*)d_in[18];
    const float* bwd1_b = (const float*)d_in[19];
    const float* rl0_w  = (const float*)d_in[20];
    const float* rl0_b  = (const float*)d_in[21];
    const float* rl1_w  = (const float*)d_in[22];
    const float* rl1_b  = (const float*)d_in[23];
    const float* cost0_w = (const float*)d_in[24];
    const float* cost0_b = (const float*)d_in[25];
    const float* cost1_w = (const float*)d_in[26];
    const float* cost1_b = (const float*)d_in[27];
    const float* pol_w   = (const float*)d_in[28];
    const float* pol_b   = (const float*)d_in[29];

    const int N = in_sizes[0] / F_IN;
    const int S = out_size;   // B*D

    cudaFuncSetAttribute(phaseA_kernel,
                         cudaFuncAttributeMaxDynamicSharedMemorySize,
                         SMEM_A_BYTES);

    // 1) zero the segment accumulator (graph-replay safe)
    {
        int n4 = (S_SEG * H1C) / 4;
        zero_kernel<<<(n4 + 255) / 256, 256>>>(n4);
    }

    // 2) fused dual-branch MLP + segment reduction
    phaseA_kernel<<<GRID_A, BLK_A, SMEM_A_BYTES>>>(
        x, sid, tfc0_w, tfc0_b, tfc1_w, tfc1_b,
        rl0_w, rl0_b, rl1_w, rl1_b, N);

    // 3) per-segment heads + cost MLP + policy
    phaseB_kernel<<<128, 256>>>(
        fwd0_w, fwd0_b, fwd1_w, fwd1_b,
        com0_w, com0_b, com1_w, com1_b,
        bwd0_w, bwd0_b, bwd1_w, bwd1_b,
        cost0_w, cost0_b, cost1_w, cost1_b,
        pol_w, pol_b,
        (float*)d_out, S);
}

// round 3
// speedup vs baseline: 3.7253x; 3.7253x over previous
#include <cuda_runtime.h>
#include <cstdint>

// ===========================================================================
// Model_55611236549533 — sm_103a via baseline PTX mma.sync (tf32 HMMA).
//   x:[N,64] fp32, segment_ids sorted, S=16384.
//   Per 64-row tile (persistent CTAs, 1/SM, 8 warps):
//     L0: X[64x64] @ W0[64x256] (+bias0, relu) -> H (tf32 bits in smem)
//     L1: H[64x128 per branch] @ W1[128x32] (+bias1, relu) -> Gs
//     sorted-run segment reduce -> atomics into g_segbuf
//   PhaseB: per-segment heads (unchanged, validated in round 1).
// ===========================================================================

#define F_IN   64
#define S_SEG  16384
#define TILE   64
#define BLK    256
#define GRID_A 148

// smem strides (floats) — chosen for conflict-free mma fragment loads
#define LDX  68    // 68  % 32*? -> row*4 banks
#define LDH  260   // 260 mod 32 = 4
#define LDW0 264   // 264 mod 32 = 8
#define LDW1 40    // 40  mod 32 = 8
#define LDGS 68

// smem float offsets
#define O_W0   0
#define O_W1A  (O_W0  + 64 * LDW0)        // 16896
#define O_W1B  (O_W1A + 128 * LDW1)       // 22016
#define O_B0   (O_W1B + 128 * LDW1)       // 27136
#define O_B1   (O_B0  + 256)              // 27392
#define O_X    (O_B1  + 64)               // 27456
#define O_H    (O_X   + TILE * LDX)       // 31808
#define O_GS   (O_H   + TILE * LDH)       // 48448
#define O_SID  (O_GS  + TILE * LDGS)      // 52800 (2 x 64 ints)
#define SMEM_FLOATS (O_SID + 128)
#define SMEM_BYTES  (SMEM_FLOATS * 4)     // 211712

__device__ float g_segbuf[S_SEG * 64];    // [seg][0:32 tfc | 32:64 rl]

// ---------------------------------------------------------------- helpers
__device__ __forceinline__ uint32_t f2tf(float f) {
    uint32_t u;
    asm("cvt.rna.tf32.f32 %0, %1;" : "=r"(u) : "f"(f));
    return u;
}
__device__ __forceinline__ uint32_t fbits(float f) { return __float_as_uint(f); }

__device__ __forceinline__ void mma_tf32(float* d, const uint32_t* a,
                                         const uint32_t* b) {
    asm volatile(
        "mma.sync.aligned.m16n8k8.row.col.f32.tf32.tf32.f32 "
        "{%0,%1,%2,%3}, {%4,%5,%6,%7}, {%8,%9}, {%0,%1,%2,%3};"
        : "+f"(d[0]), "+f"(d[1]), "+f"(d[2]), "+f"(d[3])
        : "r"(a[0]), "r"(a[1]), "r"(a[2]), "r"(a[3]), "r"(b[0]), "r"(b[1]));
}

// ------------------------------------------------------------ zero segbuf
__global__ void zero_kernel(int n4) {
    int i = blockIdx.x * blockDim.x + threadIdx.x;
    if (i < n4)
        reinterpret_cast<float4*>(g_segbuf)[i] = make_float4(0.f, 0.f, 0.f, 0.f);
}

// -------------------------------------------------------------- phase A
__global__ __launch_bounds__(BLK, 1)
void phaseA_mma(const float* __restrict__ x,
                const int*   __restrict__ seg_ids,
                const float* __restrict__ tfc0_w, const float* __restrict__ tfc0_b,
                const float* __restrict__ tfc1_w, const float* __restrict__ tfc1_b,
                const float* __restrict__ rl0_w,  const float* __restrict__ rl0_b,
                const float* __restrict__ rl1_w,  const float* __restrict__ rl1_b,
                int N)
{
    extern __shared__ float sm[];
    float* W0s = sm + O_W0;
    float* W1s[2] = { sm + O_W1A, sm + O_W1B };
    float* B0s = sm + O_B0;
    float* B1s = sm + O_B1;
    float* Xs  = sm + O_X;
    float* Hs  = sm + O_H;
    float* Gs  = sm + O_GS;
    int*   sid_s = (int*)(sm + O_SID);

    const int tid  = threadIdx.x;
    const int wid  = tid >> 5;
    const int lane = tid & 31;
    const int lg   = lane >> 2;     // group id 0..7
    const int lt   = lane & 3;      // thread-in-group 0..3

    // ---- stage weights as tf32 bits (once) ----
    for (int i = tid; i < 64 * 128; i += BLK) {        // W0 halves
        int k = i >> 7, n = i & 127;
        W0s[k * LDW0 + n]       = __uint_as_float(f2tf(tfc0_w[i]));
        W0s[k * LDW0 + 128 + n] = __uint_as_float(f2tf(rl0_w[i]));
    }
    for (int i = tid; i < 128 * 32; i += BLK) {        // W1 halves
        int k = i >> 5, n = i & 31;
        W1s[0][k * LDW1 + n] = __uint_as_float(f2tf(tfc1_w[i]));
        W1s[1][k * LDW1 + n] = __uint_as_float(f2tf(rl1_w[i]));
    }
    if (tid < 128) { B0s[tid] = tfc0_b[tid]; B0s[128 + tid] = rl0_b[tid]; }
    if (tid < 32)  { B1s[tid] = tfc1_b[tid]; B1s[32 + tid] = rl1_b[tid]; }

    const int ntiles = (N + TILE - 1) / TILE;

    // ---- stage first tile ----
    int tile = blockIdx.x;
    {
        int r = tid >> 2, q = tid & 3;
        long g = (long)tile * TILE + r;
        #pragma unroll
        for (int i = 0; i < 4; ++i) {
            float4 v = make_float4(0.f, 0.f, 0.f, 0.f);
            if (tile < ntiles && g < N)
                v = *reinterpret_cast<const float4*>(&x[g * F_IN + q * 16 + i * 4]);
            uint4 u = make_uint4(f2tf(v.x), f2tf(v.y), f2tf(v.z), f2tf(v.w));
            *reinterpret_cast<uint4*>(&Xs[r * LDX + q * 16 + i * 4]) = u;
        }
        if (tid < TILE) {
            long gi = (long)tile * TILE + tid;
            sid_s[tid] = (tile < ntiles && gi < N) ? seg_ids[gi] : -1;
        }
    }
    __syncthreads();

    // warp roles
    const int mp0 = wid & 1;            // L0 row half (32 rows)
    const int cq  = wid >> 1;           // L0 col quarter (64 cols)
    const int mp1 = wid & 1;            // L1 row half
    const int np1 = (wid >> 1) & 1;     // L1 col half (16 cols)
    const int br  = wid >> 2;           // L1 branch

    int p = 0;
    for (; tile < ntiles; tile += GRID_A) {
        const int valid = min(TILE, N - tile * TILE);
        const int ntile = tile + GRID_A;

        // ---- prefetch next tile into registers ----
        float4 px[4];
        int    psid = -1;
        {
            int r = tid >> 2, q = tid & 3;
            long g = (long)ntile * TILE + r;
            bool ok = (ntile < ntiles) && (g < N);
            #pragma unroll
            for (int i = 0; i < 4; ++i) {
                px[i] = make_float4(0.f, 0.f, 0.f, 0.f);
                if (ok)
                    px[i] = *reinterpret_cast<const float4*>(
                        &x[g * F_IN + q * 16 + i * 4]);
            }
            long gi = (long)ntile * TILE + tid;
            if (tid < TILE && ntile < ntiles && gi < N) psid = seg_ids[gi];
        }

        // =============== Layer 0: X @ W0 ===============
        {
            float acc[2][8][4];
            #pragma unroll
            for (int m = 0; m < 2; ++m)
                #pragma unroll
                for (int nb = 0; nb < 8; ++nb)
                    #pragma unroll
                    for (int j = 0; j < 4; ++j) acc[m][nb][j] = 0.f;

            #pragma unroll
            for (int kb = 0; kb < 8; ++kb) {
                uint32_t a[2][4];
                #pragma unroll
                for (int m = 0; m < 2; ++m) {
                    const float* ap = &Xs[(mp0 * 32 + m * 16 + lg) * LDX + kb * 8 + lt];
                    a[m][0] = fbits(ap[0]);
                    a[m][1] = fbits(ap[8 * LDX]);
                    a[m][2] = fbits(ap[4]);
                    a[m][3] = fbits(ap[8 * LDX + 4]);
                }
                #pragma unroll
                for (int nb = 0; nb < 8; ++nb) {
                    const float* bp = &W0s[(kb * 8 + lt) * LDW0 + cq * 64 + nb * 8 + lg];
                    uint32_t b[2] = { fbits(bp[0]), fbits(bp[4 * LDW0]) };
                    mma_tf32(acc[0][nb], a[0], b);
                    mma_tf32(acc[1][nb], a[1], b);
                }
            }
            // bias0 + relu -> H (tf32 bits)
            #pragma unroll
            for (int nb = 0; nb < 8; ++nb) {
                int cpair = cq * 64 + nb * 8 + 2 * lt;
                float2 bv = *reinterpret_cast<const float2*>(&B0s[cpair]);
                #pragma unroll
                for (int m = 0; m < 2; ++m) {
                    int row = mp0 * 32 + m * 16 + lg;
                    uint2 lo = make_uint2(
                        f2tf(fmaxf(acc[m][nb][0] + bv.x, 0.f)),
                        f2tf(fmaxf(acc[m][nb][1] + bv.y, 0.f)));
                    uint2 hi = make_uint2(
                        f2tf(fmaxf(acc[m][nb][2] + bv.x, 0.f)),
                        f2tf(fmaxf(acc[m][nb][3] + bv.y, 0.f)));
                    *reinterpret_cast<uint2*>(&Hs[row * LDH + cpair]) = lo;
                    *reinterpret_cast<uint2*>(&Hs[(row + 8) * LDH + cpair]) = hi;
                }
            }
        }
        __syncthreads();

        // ---- store prefetched X/sid (X free after L0) ----
        {
            int r = tid >> 2, q = tid & 3;
            #pragma unroll
            for (int i = 0; i < 4; ++i) {
                uint4 u = make_uint4(f2tf(px[i].x), f2tf(px[i].y),
                                     f2tf(px[i].z), f2tf(px[i].w));
                *reinterpret_cast<uint4*>(&Xs[r * LDX + q * 16 + i * 4]) = u;
            }
            if (tid < TILE) sid_s[(p ^ 1) * TILE + tid] = psid;
        }

        // =============== Layer 1: H @ W1[br] ===============
        {
            float acc[2][2][4];
            #pragma unroll
            for (int m = 0; m < 2; ++m)
                #pragma unroll
                for (int nb = 0; nb < 2; ++nb)
                    #pragma unroll
                    for (int j = 0; j < 4; ++j) acc[m][nb][j] = 0.f;

            const float* w1 = W1s[br];
            #pragma unroll
            for (int kb = 0; kb < 16; ++kb) {
                uint32_t a[2][4];
                #pragma unroll
                for (int m = 0; m < 2; ++m) {
                    const float* ap =
                        &Hs[(mp1 * 32 + m * 16 + lg) * LDH + br * 128 + kb * 8 + lt];
                    a[m][0] = fbits(ap[0]);
                    a[m][1] = fbits(ap[8 * LDH]);
                    a[m][2] = fbits(ap[4]);
                    a[m][3] = fbits(ap[8 * LDH + 4]);
                }
                #pragma unroll
                for (int nb = 0; nb < 2; ++nb) {
                    const float* bp = &w1[(kb * 8 + lt) * LDW1 + np1 * 16 + nb * 8 + lg];
                    uint32_t b[2] = { fbits(bp[0]), fbits(bp[4 * LDW1]) };
                    mma_tf32(acc[0][nb], a[0], b);
                    mma_tf32(acc[1][nb], a[1], b);
                }
            }
            // bias1 + relu -> Gs (fp32)
            #pragma unroll
            for (int nb = 0; nb < 2; ++nb) {
                int colg = br * 32 + np1 * 16 + nb * 8 + 2 * lt;
                float2 bv = *reinterpret_cast<const float2*>(&B1s[colg]);
                #pragma unroll
                for (int m = 0; m < 2; ++m) {
                    int row = mp1 * 32 + m * 16 + lg;
                    float2 lo = make_float2(fmaxf(acc[m][nb][0] + bv.x, 0.f),
                                            fmaxf(acc[m][nb][1] + bv.y, 0.f));
                    float2 hi = make_float2(fmaxf(acc[m][nb][2] + bv.x, 0.f),
                                            fmaxf(acc[m][nb][3] + bv.y, 0.f));
                    *reinterpret_cast<float2*>(&Gs[row * LDGS + colg]) = lo;
                    *reinterpret_cast<float2*>(&Gs[(row + 8) * LDGS + colg]) = hi;
                }
            }
        }
        __syncthreads();

        // ---- sorted-run segment reduction (4 chunks x 64 cols) ----
        {
            const int chunk = tid >> 6, c = tid & 63;
            const int rbeg = chunk * 16;
            const int rend = min(rbeg + 16, valid);
            const int* sid = &sid_s[p * TILE];
            if (rbeg < rend) {
                int prev = sid[rbeg];
                float run = 0.f;
                for (int r = rbeg; r < rend; ++r) {
                    int sd = sid[r];
                    if (sd != prev) {
                        atomicAdd(&g_segbuf[prev * 64 + c], run);
                        run = 0.f; prev = sd;
                    }
                    run += Gs[r * LDGS + c];
                }
                atomicAdd(&g_segbuf[prev * 64 + c], run);
            }
        }
        p ^= 1;
        // next iter's layer0 begins only after the post-L0 sync of that iter,
        // which orders this reduction before any buffer reuse.
    }
}

// ---------------------------------------------------------------- phase B
__global__ __launch_bounds__(256)
void phaseB_kernel(const float* __restrict__ fwd0_w, const float* __restrict__ fwd0_b,
                   const float* __restrict__ fwd1_w, const float* __restrict__ fwd1_b,
                   const float* __restrict__ com0_w, const float* __restrict__ com0_b,
                   const float* __restrict__ com1_w, const float* __restrict__ com1_b,
                   const float* __restrict__ bwd0_w, const float* __restrict__ bwd0_b,
                   const float* __restrict__ bwd1_w, const float* __restrict__ bwd1_b,
                   const float* __restrict__ cost0_w, const float* __restrict__ cost0_b,
                   const float* __restrict__ cost1_w, const float* __restrict__ cost1_b,
                   const float* __restrict__ pol_w,   const float* __restrict__ pol_b,
                   float* __restrict__ out, int S)
{
    __shared__ float s_f0[32 * 64], s_c0[32 * 64], s_b0[32 * 64];
    __shared__ float s_f0b[64], s_c0b[64], s_b0b[64];
    __shared__ float s_f1[64], s_c1[64], s_b1[64];
    __shared__ float s_k0[3 * 64], s_k0b[64];
    __shared__ float s_k1[64 * 32], s_k1b[32];
    __shared__ float s_pol[64];
    __shared__ float s_scal[4];

    const int t = threadIdx.x;
    for (int i = t; i < 32 * 64; i += 256) {
        s_f0[i] = fwd0_w[i]; s_c0[i] = com0_w[i]; s_b0[i] = bwd0_w[i];
    }
    for (int i = t; i < 64 * 32; i += 256) s_k1[i] = cost1_w[i];
    if (t < 64) {
        s_f0b[t] = fwd0_b[t]; s_c0b[t] = com0_b[t]; s_b0b[t] = bwd0_b[t];
        s_f1[t] = fwd1_w[t];  s_c1[t] = com1_w[t];  s_b1[t] = bwd1_w[t];
        s_k0b[t] = cost0_b[t]; s_pol[t] = pol_w[t];
    }
    if (t < 3 * 64) s_k0[t] = cost0_w[t];
    if (t < 32) s_k1b[t] = cost1_b[t];
    if (t == 0) {
        s_scal[0] = fwd1_b[0]; s_scal[1] = com1_b[0];
        s_scal[2] = bwd1_b[0]; s_scal[3] = pol_b[0];
    }
    __syncthreads();

    const int l = t & 31;
    const int warp = (blockIdx.x * blockDim.x + t) >> 5;
    const int nwarps = (gridDim.x * blockDim.x) >> 5;

    for (int s = warp; s < S; s += nwarps) {
        const float st = g_segbuf[s * 64 + l];
        const float sr = g_segbuf[s * 64 + 32 + l];

        float hf0 = s_f0b[l], hf1 = s_f0b[l + 32];
        float hc0 = s_c0b[l], hc1 = s_c0b[l + 32];
        float hb0 = s_b0b[l], hb1 = s_b0b[l + 32];
        #pragma unroll
        for (int k = 0; k < 32; ++k) {
            float sk = __shfl_sync(0xffffffffu, st, k);
            hf0 = fmaf(sk, s_f0[k * 64 + l],      hf0);
            hf1 = fmaf(sk, s_f0[k * 64 + l + 32], hf1);
            hc0 = fmaf(sk, s_c0[k * 64 + l],      hc0);
            hc1 = fmaf(sk, s_c0[k * 64 + l + 32], hc1);
            hb0 = fmaf(sk, s_b0[k * 64 + l],      hb0);
            hb1 = fmaf(sk, s_b0[k * 64 + l + 32], hb1);
        }
        float vf = fmaxf(hf0, 0.f) * s_f1[l] + fmaxf(hf1, 0.f) * s_f1[l + 32];
        float vc = fmaxf(hc0, 0.f) * s_c1[l] + fmaxf(hc1, 0.f) * s_c1[l + 32];
        float vb = fmaxf(hb0, 0.f) * s_b1[l] + fmaxf(hb1, 0.f) * s_b1[l + 32];
        #pragma unroll
        for (int o = 16; o > 0; o >>= 1) {
            vf += __shfl_xor_sync(0xffffffffu, vf, o);
            vc += __shfl_xor_sync(0xffffffffu, vc, o);
            vb += __shfl_xor_sync(0xffffffffu, vb, o);
        }
        const float fwd = vf + s_scal[0];
        const float com = vc + s_scal[1];
        const float bwd = vb + s_scal[2];

        float c1a = fmaf(fwd, s_k0[l],
                    fmaf(com, s_k0[64 + l],
                    fmaf(bwd, s_k0[128 + l], s_k0b[l])));
        float c1b = fmaf(fwd, s_k0[l + 32],
                    fmaf(com, s_k0[64 + l + 32],
                    fmaf(bwd, s_k0[128 + l + 32], s_k0b[l + 32])));
        c1a = fmaxf(c1a, 0.f);
        c1b = fmaxf(c1b, 0.f);

        float c2 = s_k1b[l];
        #pragma unroll
        for (int jj = 0; jj < 32; ++jj) {
            float a = __shfl_sync(0xffffffffu, c1a, jj);
            float b = __shfl_sync(0xffffffffu, c1b, jj);
            c2 = fmaf(a, s_k1[jj * 32 + l], c2);
            c2 = fmaf(b, s_k1[(jj + 32) * 32 + l], c2);
        }
        c2 = fmaxf(c2, 0.f);

        float v = fmaf(sr, s_pol[l], c2 * s_pol[l + 32]);
        #pragma unroll
        for (int o = 16; o > 0; o >>= 1)
            v += __shfl_xor_sync(0xffffffffu, v, o);
        if (l == 0) out[s] = v + s_scal[3];
    }
}

// ----------------------------------------------------------------- launch
extern "C" void kernel_launch(void* const* d_in, const int* in_sizes, int n_in,
                              void* d_out, int out_size)
{
    const float* x      = (const float*)d_in[0];
    const int*   sid    = (const int*)  d_in[1];
    const float* tfc0_w = (const float*)d_in[4];
    const float* tfc0_b = (const float*)d_in[5];
    const float* tfc1_w = (const float*)d_in[6];
    const float* tfc1_b = (const float*)d_in[7];
    const float* fwd0_w = (const float*)d_in[8];
    const float* fwd0_b = (const float*)d_in[9];
    const float* fwd1_w = (const float*)d_in[10];
    const float* fwd1_b = (const float*)d_in[11];
    const float* com0_w = (const float*)d_in[12];
    const float* com0_b = (const float*)d_in[13];
    const float* com1_w = (const float*)d_in[14];
    const float* com1_b = (const float*)d_in[15];
    const float* bwd0_w = (const float*)d_in[16];
    const float* bwd0_b = (const float*)d_in[17];
    const float* bwd1_w = (const float*)d_in[18];
    const float* bwd1_b = (const float*)d_in[19];
    const float* rl0_w  = (const float*)d_in[20];
    const float* rl0_b  = (const float*)d_in[21];
    const float* rl1_w  = (const float*)d_in[22];
    const float* rl1_b  = (const float*)d_in[23];
    const float* cost0_w = (const float*)d_in[24];
    const float* cost0_b = (const float*)d_in[25];
    const float* cost1_w = (const float*)d_in[26];
    const float* cost1_b = (const float*)d_in[27];
    const float* pol_w   = (const float*)d_in[28];
    const float* pol_b   = (const float*)d_in[29];

    const int N = in_sizes[0] / F_IN;
    const int S = out_size;

    static int configured = 0;
    if (!configured) {
        cudaFuncSetAttribute(phaseA_mma,
                             cudaFuncAttributeMaxDynamicSharedMemorySize,
                             SMEM_BYTES);
        configured = 1;
    }

    {
        int n4 = (S_SEG * 64) / 4;
        zero_kernel<<<(n4 + 255) / 256, 256>>>(n4);
    }

    phaseA_mma<<<GRID_A, BLK, SMEM_BYTES>>>(
        x, sid, tfc0_w, tfc0_b, tfc1_w, tfc1_b,
        rl0_w, rl0_b, rl1_w, rl1_b, N);

    phaseB_kernel<<<128, 256>>>(
        fwd0_w, fwd0_b, fwd1_w, fwd1_b,
        com0_w, com0_b, com1_w, com1_b,
        bwd0_w, bwd0_b, bwd1_w, bwd1_b,
        cost0_w, cost0_b, cost1_w, cost1_b,
        pol_w, pol_b,
        (float*)d_out, S);
}

// round 4
// speedup vs baseline: 6.5343x; 1.7541x over previous
#include <cuda_runtime.h>
#include <cuda_fp16.h>
#include <cstdint>

// ===========================================================================
// Model_55611236549533 — sm_103a, baseline-PTX fp16 mma.m16n8k16 + ldmatrix.
//   Per 64-row tile (148 persistent CTAs, 8 warps):
//     L0: X[64x64]h @ W0[64x256]h (+b0, relu) -> H fp16 smem
//     L1: H @ W1[128x32 per branch]h (+b1, relu) -> Gs fp32 smem
//     sorted-run segment reduce -> atomics into g_segbuf
//   Weight B-fragments live in registers (preloaded once per CTA).
// ===========================================================================

#define F_IN   64
#define S_SEG  16384
#define TILE   64
#define BLK    256
#define GRID_A 148

// half strides
#define LDXH  72     // X row stride (halves)  -> 144 B
#define LDHH  264    // H row stride (halves)  -> 528 B
#define LDW0H 72     // W0 [n][k] stride       -> 144 B
#define LDW1H 136    // W1 [n][k] stride       -> 272 B
#define LDGS  72     // Gs row stride (floats) -> 288 B

// smem byte offsets (all 16B aligned)
#define O_W0   0                         // 256 * 144            = 36864
#define O_W1   36864                     // 2 * 32 * 272         = 17408
#define O_X    54272                     // 64 * 144             =  9216
#define O_H    63488                     // 64 * 528             = 33792
#define O_GS   97280                     // 64 * 288             = 18432
#define O_B0   115712                    // 256 f32              =  1024
#define O_B1   116736                    // 64 f32               =   256
#define O_SID  116992                    // 128 int              =   512
#define SMEM_BYTES 117504

__device__ float g_segbuf[S_SEG * 64];   // [seg][0:32 tfc | 32:64 rl]

// ---------------------------------------------------------------- PTX utils
__device__ __forceinline__ uint32_t smem_u32(const void* p) {
    uint32_t a;
    asm("{ .reg .u64 t; cvta.to.shared.u64 t, %1; cvt.u32.u64 %0, t; }"
        : "=r"(a) : "l"(p));
    return a;
}
__device__ __forceinline__ void ldmx4(uint32_t* r, uint32_t addr) {
    asm volatile("ldmatrix.sync.aligned.m8n8.x4.shared.b16 {%0,%1,%2,%3}, [%4];"
                 : "=r"(r[0]), "=r"(r[1]), "=r"(r[2]), "=r"(r[3]) : "r"(addr));
}
__device__ __forceinline__ void ldmx2(uint32_t* r, uint32_t addr) {
    asm volatile("ldmatrix.sync.aligned.m8n8.x2.shared.b16 {%0,%1}, [%2];"
                 : "=r"(r[0]), "=r"(r[1]) : "r"(addr));
}
__device__ __forceinline__ void mma_f16(float* d, const uint32_t* a,
                                        const uint32_t* b) {
    asm volatile(
        "mma.sync.aligned.m16n8k16.row.col.f32.f16.f16.f32 "
        "{%0,%1,%2,%3}, {%4,%5,%6,%7}, {%8,%9}, {%0,%1,%2,%3};"
        : "+f"(d[0]), "+f"(d[1]), "+f"(d[2]), "+f"(d[3])
        : "r"(a[0]), "r"(a[1]), "r"(a[2]), "r"(a[3]), "r"(b[0]), "r"(b[1]));
}

// ------------------------------------------------------------ zero segbuf
__global__ void zero_kernel(int n4) {
    int i = blockIdx.x * blockDim.x + threadIdx.x;
    if (i < n4)
        reinterpret_cast<float4*>(g_segbuf)[i] = make_float4(0.f, 0.f, 0.f, 0.f);
}

// -------------------------------------------------------------- phase A
__global__ __launch_bounds__(BLK, 1)
void phaseA_mma(const float* __restrict__ x,
                const int*   __restrict__ seg_ids,
                const float* __restrict__ tfc0_w, const float* __restrict__ tfc0_b,
                const float* __restrict__ tfc1_w, const float* __restrict__ tfc1_b,
                const float* __restrict__ rl0_w,  const float* __restrict__ rl0_b,
                const float* __restrict__ rl1_w,  const float* __restrict__ rl1_b,
                int N)
{
    extern __shared__ char smc[];
    __half* W0s = (__half*)(smc + O_W0);   // [n=256][k=64] stride LDW0H
    __half* W1s = (__half*)(smc + O_W1);   // [br][n=32][k=128] stride LDW1H
    __half* Xs  = (__half*)(smc + O_X);    // [64][64] stride LDXH
    __half* Hs  = (__half*)(smc + O_H);    // [64][256] stride LDHH
    float*  Gs  = (float*)(smc + O_GS);    // [64][64] stride LDGS
    float*  B0s = (float*)(smc + O_B0);
    float*  B1s = (float*)(smc + O_B1);
    int*    sid_s = (int*)(smc + O_SID);
    const uint32_t smb = smem_u32(smc);

    const int tid  = threadIdx.x;
    const int wid  = tid >> 5;
    const int lane = tid & 31;
    const int lg   = lane >> 2;       // row in d-fragment
    const int lt   = lane & 3;        // col-pair in d-fragment

    // ---- stage weights as fp16, [n][k] layout ----
    for (int i = tid; i < 64 * 128; i += BLK) {        // W0 per branch
        int k = i >> 7, n = i & 127;
        W0s[n * LDW0H + k]         = __float2half_rn(tfc0_w[i]);
        W0s[(n + 128) * LDW0H + k] = __float2half_rn(rl0_w[i]);
    }
    for (int i = tid; i < 128 * 32; i += BLK) {        // W1 per branch
        int k = i >> 5, n = i & 31;
        W1s[n * LDW1H + k]              = __float2half_rn(tfc1_w[i]);
        W1s[(32 + n) * LDW1H + k]       = __float2half_rn(rl1_w[i]);
    }
    if (tid < 128) { B0s[tid] = tfc0_b[tid]; B0s[128 + tid] = rl0_b[tid]; }
    if (tid < 32)  { B1s[tid] = tfc1_b[tid]; B1s[32 + tid] = rl1_b[tid]; }

    const int ntiles = (N + TILE - 1) / TILE;

    // ---- stage first X tile + sids ----
    int tile = blockIdx.x;
    {
        int r = tid >> 2, q = (tid & 3) * 16;
        long g = (long)tile * TILE + r;
        bool ok = (tile < ntiles) && (g < N);
        #pragma unroll
        for (int i = 0; i < 4; ++i) {
            float4 v = make_float4(0.f, 0.f, 0.f, 0.f);
            if (ok) v = *reinterpret_cast<const float4*>(&x[g * F_IN + q + i * 4]);
            __half2 h0 = __floats2half2_rn(v.x, v.y);
            __half2 h1 = __floats2half2_rn(v.z, v.w);
            *reinterpret_cast<__half2*>(&Xs[r * LDXH + q + i * 4])     = h0;
            *reinterpret_cast<__half2*>(&Xs[r * LDXH + q + i * 4 + 2]) = h1;
        }
        if (tid < TILE) {
            long gi = (long)tile * TILE + tid;
            sid_s[tid] = (tile < ntiles && gi < N) ? seg_ids[gi] : -1;
        }
    }
    __syncthreads();

    // ---- warp roles ----
    const int mh0 = wid & 1;          // L0: 32-row half
    const int no  = wid >> 1;         // L0: 64-col octet (8 n8-tiles)
    const int br  = wid >> 2;         // L1: branch
    const int mh1 = wid & 1;          // L1: 32-row half
    const int nq  = (wid >> 1) & 1;   // L1: 16-col quarter (2 n8-tiles)

    // ---- preload weight B-fragments into registers ----
    uint32_t bw0[8][4][2];            // [n8-tile][k16][2]
    #pragma unroll
    for (int j = 0; j < 8; ++j)
        #pragma unroll
        for (int k2 = 0; k2 < 4; ++k2) {
            int n = no * 64 + j * 8 + (lane & 7);
            int k = k2 * 16 + ((lane >> 3) & 1) * 8;
            ldmx2(bw0[j][k2], smb + O_W0 + (n * LDW0H + k) * 2);
        }
    uint32_t bw1[2][8][2];            // [n8-tile][k16][2]
    #pragma unroll
    for (int jn = 0; jn < 2; ++jn)
        #pragma unroll
        for (int kk = 0; kk < 8; ++kk) {
            int n = br * 32 + nq * 16 + jn * 8 + (lane & 7);
            int k = kk * 16 + ((lane >> 3) & 1) * 8;
            ldmx2(bw1[jn][kk], smb + O_W1 + (n * LDW1H + k) * 2);
        }

    int p = 0;
    for (; tile < ntiles; tile += GRID_A) {
        const int valid = min(TILE, N - tile * TILE);
        const int ntile = tile + GRID_A;

        // ---- prefetch next tile ----
        float4 px[4];
        int    psid = -1;
        {
            int r = tid >> 2, q = (tid & 3) * 16;
            long g = (long)ntile * TILE + r;
            bool ok = (ntile < ntiles) && (g < N);
            #pragma unroll
            for (int i = 0; i < 4; ++i) {
                px[i] = make_float4(0.f, 0.f, 0.f, 0.f);
                if (ok) px[i] = *reinterpret_cast<const float4*>(
                            &x[g * F_IN + q + i * 4]);
            }
            long gi = (long)ntile * TILE + tid;
            if (tid < TILE && ntile < ntiles && gi < N) psid = seg_ids[gi];
        }

        // =============== Layer 0 ===============
        {
            float acc[2][8][4];
            #pragma unroll
            for (int m = 0; m < 2; ++m)
                #pragma unroll
                for (int j = 0; j < 8; ++j)
                    #pragma unroll
                    for (int v = 0; v < 4; ++v) acc[m][j][v] = 0.f;

            #pragma unroll
            for (int k2 = 0; k2 < 4; ++k2) {
                uint32_t a[2][4];
                #pragma unroll
                for (int m = 0; m < 2; ++m) {
                    int row = mh0 * 32 + m * 16 + (lane & 15);
                    int kc  = k2 * 16 + ((lane >> 4) << 3);
                    ldmx4(a[m], smb + O_X + (row * LDXH + kc) * 2);
                }
                #pragma unroll
                for (int j = 0; j < 8; ++j) {
                    mma_f16(acc[0][j], a[0], bw0[j][k2]);
                    mma_f16(acc[1][j], a[1], bw0[j][k2]);
                }
            }
            // bias + relu -> H fp16
            #pragma unroll
            for (int j = 0; j < 8; ++j) {
                int col = no * 64 + j * 8 + 2 * lt;
                float2 bv = *reinterpret_cast<const float2*>(&B0s[col]);
                #pragma unroll
                for (int m = 0; m < 2; ++m) {
                    int row = mh0 * 32 + m * 16 + lg;
                    __half2 lo = __floats2half2_rn(
                        fmaxf(acc[m][j][0] + bv.x, 0.f),
                        fmaxf(acc[m][j][1] + bv.y, 0.f));
                    __half2 hi = __floats2half2_rn(
                        fmaxf(acc[m][j][2] + bv.x, 0.f),
                        fmaxf(acc[m][j][3] + bv.y, 0.f));
                    *reinterpret_cast<__half2*>(&Hs[row * LDHH + col]) = lo;
                    *reinterpret_cast<__half2*>(&Hs[(row + 8) * LDHH + col]) = hi;
                }
            }
        }
        __syncthreads();

        // ---- store prefetched X + sid (Xs free after L0) ----
        {
            int r = tid >> 2, q = (tid & 3) * 16;
            #pragma unroll
            for (int i = 0; i < 4; ++i) {
                __half2 h0 = __floats2half2_rn(px[i].x, px[i].y);
                __half2 h1 = __floats2half2_rn(px[i].z, px[i].w);
                *reinterpret_cast<__half2*>(&Xs[r * LDXH + q + i * 4])     = h0;
                *reinterpret_cast<__half2*>(&Xs[r * LDXH + q + i * 4 + 2]) = h1;
            }
            if (tid < TILE) sid_s[(p ^ 1) * TILE + tid] = psid;
        }

        // =============== Layer 1 ===============
        {
            float acc[2][2][4];
            #pragma unroll
            for (int m = 0; m < 2; ++m)
                #pragma unroll
                for (int jn = 0; jn < 2; ++jn)
                    #pragma unroll
                    for (int v = 0; v < 4; ++v) acc[m][jn][v] = 0.f;

            #pragma unroll
            for (int kk = 0; kk < 8; ++kk) {
                uint32_t a[2][4];
                #pragma unroll
                for (int m = 0; m < 2; ++m) {
                    int row = mh1 * 32 + m * 16 + (lane & 15);
                    int kc  = br * 128 + kk * 16 + ((lane >> 4) << 3);
                    ldmx4(a[m], smb + O_H + (row * LDHH + kc) * 2);
                }
                #pragma unroll
                for (int jn = 0; jn < 2; ++jn) {
                    mma_f16(acc[0][jn], a[0], bw1[jn][kk]);
                    mma_f16(acc[1][jn], a[1], bw1[jn][kk]);
                }
            }
            // bias + relu -> Gs fp32
            #pragma unroll
            for (int jn = 0; jn < 2; ++jn) {
                int col = br * 32 + nq * 16 + jn * 8 + 2 * lt;
                float2 bv = *reinterpret_cast<const float2*>(&B1s[col]);
                #pragma unroll
                for (int m = 0; m < 2; ++m) {
                    int row = mh1 * 32 + m * 16 + lg;
                    float2 lo = make_float2(fmaxf(acc[m][jn][0] + bv.x, 0.f),
                                            fmaxf(acc[m][jn][1] + bv.y, 0.f));
                    float2 hi = make_float2(fmaxf(acc[m][jn][2] + bv.x, 0.f),
                                            fmaxf(acc[m][jn][3] + bv.y, 0.f));
                    *reinterpret_cast<float2*>(&Gs[row * LDGS + col]) = lo;
                    *reinterpret_cast<float2*>(&Gs[(row + 8) * LDGS + col]) = hi;
                }
            }
        }
        __syncthreads();

        // ---- sorted-run segment reduction ----
        {
            const int chunk = tid >> 6, c = tid & 63;
            const int rbeg = chunk * 16;
            const int rend = min(rbeg + 16, valid);
            const int* sid = &sid_s[p * TILE];
            if (rbeg < rend) {
                int prev = sid[rbeg];
                float run = 0.f;
                for (int r = rbeg; r < rend; ++r) {
                    int sd = sid[r];
                    if (sd != prev) {
                        atomicAdd(&g_segbuf[prev * 64 + c], run);
                        run = 0.f; prev = sd;
                    }
                    run += Gs[r * LDGS + c];
                }
                atomicAdd(&g_segbuf[prev * 64 + c], run);
            }
        }
        p ^= 1;
        // safety: a warp can only reach the next iteration's Gs writes after
        // passing the next sync1, which requires all warps done with this
        // reduction. Hs/Xs hazards covered by sync1/sync2 as in round 3.
    }
}

// ---------------------------------------------------------------- phase B
__global__ __launch_bounds__(256)
void phaseB_kernel(const float* __restrict__ fwd0_w, const float* __restrict__ fwd0_b,
                   const float* __restrict__ fwd1_w, const float* __restrict__ fwd1_b,
                   const float* __restrict__ com0_w, const float* __restrict__ com0_b,
                   const float* __restrict__ com1_w, const float* __restrict__ com1_b,
                   const float* __restrict__ bwd0_w, const float* __restrict__ bwd0_b,
                   const float* __restrict__ bwd1_w, const float* __restrict__ bwd1_b,
                   const float* __restrict__ cost0_w, const float* __restrict__ cost0_b,
                   const float* __restrict__ cost1_w, const float* __restrict__ cost1_b,
                   const float* __restrict__ pol_w,   const float* __restrict__ pol_b,
                   float* __restrict__ out, int S)
{
    __shared__ float s_f0[32 * 64], s_c0[32 * 64], s_b0[32 * 64];
    __shared__ float s_f0b[64], s_c0b[64], s_b0b[64];
    __shared__ float s_f1[64], s_c1[64], s_b1[64];
    __shared__ float s_k0[3 * 64], s_k0b[64];
    __shared__ float s_k1[64 * 32], s_k1b[32];
    __shared__ float s_pol[64];
    __shared__ float s_scal[4];

    const int t = threadIdx.x;
    for (int i = t; i < 32 * 64; i += 256) {
        s_f0[i] = fwd0_w[i]; s_c0[i] = com0_w[i]; s_b0[i] = bwd0_w[i];
    }
    for (int i = t; i < 64 * 32; i += 256) s_k1[i] = cost1_w[i];
    if (t < 64) {
        s_f0b[t] = fwd0_b[t]; s_c0b[t] = com0_b[t]; s_b0b[t] = bwd0_b[t];
        s_f1[t] = fwd1_w[t];  s_c1[t] = com1_w[t];  s_b1[t] = bwd1_w[t];
        s_k0b[t] = cost0_b[t]; s_pol[t] = pol_w[t];
    }
    if (t < 3 * 64) s_k0[t] = cost0_w[t];
    if (t < 32) s_k1b[t] = cost1_b[t];
    if (t == 0) {
        s_scal[0] = fwd1_b[0]; s_scal[1] = com1_b[0];
        s_scal[2] = bwd1_b[0]; s_scal[3] = pol_b[0];
    }
    __syncthreads();

    const int l = t & 31;
    const int warp = (blockIdx.x * blockDim.x + t) >> 5;
    const int nwarps = (gridDim.x * blockDim.x) >> 5;

    for (int s = warp; s < S; s += nwarps) {
        const float st = g_segbuf[s * 64 + l];
        const float sr = g_segbuf[s * 64 + 32 + l];

        float hf0 = s_f0b[l], hf1 = s_f0b[l + 32];
        float hc0 = s_c0b[l], hc1 = s_c0b[l + 32];
        float hb0 = s_b0b[l], hb1 = s_b0b[l + 32];
        #pragma unroll
        for (int k = 0; k < 32; ++k) {
            float sk = __shfl_sync(0xffffffffu, st, k);
            hf0 = fmaf(sk, s_f0[k * 64 + l],      hf0);
            hf1 = fmaf(sk, s_f0[k * 64 + l + 32], hf1);
            hc0 = fmaf(sk, s_c0[k * 64 + l],      hc0);
            hc1 = fmaf(sk, s_c0[k * 64 + l + 32], hc1);
            hb0 = fmaf(sk, s_b0[k * 64 + l],      hb0);
            hb1 = fmaf(sk, s_b0[k * 64 + l + 32], hb1);
        }
        float vf = fmaxf(hf0, 0.f) * s_f1[l] + fmaxf(hf1, 0.f) * s_f1[l + 32];
        float vc = fmaxf(hc0, 0.f) * s_c1[l] + fmaxf(hc1, 0.f) * s_c1[l + 32];
        float vb = fmaxf(hb0, 0.f) * s_b1[l] + fmaxf(hb1, 0.f) * s_b1[l + 32];
        #pragma unroll
        for (int o = 16; o > 0; o >>= 1) {
            vf += __shfl_xor_sync(0xffffffffu, vf, o);
            vc += __shfl_xor_sync(0xffffffffu, vc, o);
            vb += __shfl_xor_sync(0xffffffffu, vb, o);
        }
        const float fwd = vf + s_scal[0];
        const float com = vc + s_scal[1];
        const float bwd = vb + s_scal[2];

        float c1a = fmaf(fwd, s_k0[l],
                    fmaf(com, s_k0[64 + l],
                    fmaf(bwd, s_k0[128 + l], s_k0b[l])));
        float c1b = fmaf(fwd, s_k0[l + 32],
                    fmaf(com, s_k0[64 + l + 32],
                    fmaf(bwd, s_k0[128 + l + 32], s_k0b[l + 32])));
        c1a = fmaxf(c1a, 0.f);
        c1b = fmaxf(c1b, 0.f);

        float c2 = s_k1b[l];
        #pragma unroll
        for (int jj = 0; jj < 32; ++jj) {
            float a = __shfl_sync(0xffffffffu, c1a, jj);
            float b = __shfl_sync(0xffffffffu, c1b, jj);
            c2 = fmaf(a, s_k1[jj * 32 + l], c2);
            c2 = fmaf(b, s_k1[(jj + 32) * 32 + l], c2);
        }
        c2 = fmaxf(c2, 0.f);

        float v = fmaf(sr, s_pol[l], c2 * s_pol[l + 32]);
        #pragma unroll
        for (int o = 16; o > 0; o >>= 1)
            v += __shfl_xor_sync(0xffffffffu, v, o);
        if (l == 0) out[s] = v + s_scal[3];
    }
}

// ----------------------------------------------------------------- launch
extern "C" void kernel_launch(void* const* d_in, const int* in_sizes, int n_in,
                              void* d_out, int out_size)
{
    const float* x      = (const float*)d_in[0];
    const int*   sid    = (const int*)  d_in[1];
    const float* tfc0_w = (const float*)d_in[4];
    const float* tfc0_b = (const float*)d_in[5];
    const float* tfc1_w = (const float*)d_in[6];
    const float* tfc1_b = (const float*)d_in[7];
    const float* fwd0_w = (const float*)d_in[8];
    const float* fwd0_b = (const float*)d_in[9];
    const float* fwd1_w = (const float*)d_in[10];
    const float* fwd1_b = (const float*)d_in[11];
    const float* com0_w = (const float*)d_in[12];
    const float* com0_b = (const float*)d_in[13];
    const float* com1_w = (const float*)d_in[14];
    const float* com1_b = (const float*)d_in[15];
    const float* bwd0_w = (const float*)d_in[16];
    const float* bwd0_b = (const float*)d_in[17];
    const float* bwd1_w = (const float*)d_in[18];
    const float* bwd1_b = (const float*)d_in[19];
    const float* rl0_w  = (const float*)d_in[20];
    const float* rl0_b  = (const float*)d_in[21];
    const float* rl1_w  = (const float*)d_in[22];
    const float* rl1_b  = (const float*)d_in[23];
    const float* cost0_w = (const float*)d_in[24];
    const float* cost0_b = (const float*)d_in[25];
    const float* cost1_w = (const float*)d_in[26];
    const float* cost1_b = (const float*)d_in[27];
    const float* pol_w   = (const float*)d_in[28];
    const float* pol_b   = (const float*)d_in[29];

    const int N = in_sizes[0] / F_IN;
    const int S = out_size;

    static int configured = 0;
    if (!configured) {
        cudaFuncSetAttribute(phaseA_mma,
                             cudaFuncAttributeMaxDynamicSharedMemorySize,
                             SMEM_BYTES);
        configured = 1;
    }

    {
        int n4 = (S_SEG * 64) / 4;
        zero_kernel<<<(n4 + 255) / 256, 256>>>(n4);
    }

    phaseA_mma<<<GRID_A, BLK, SMEM_BYTES>>>(
        x, sid, tfc0_w, tfc0_b, tfc1_w, tfc1_b,
        rl0_w, rl0_b, rl1_w, rl1_b, N);

    phaseB_kernel<<<128, 256>>>(
        fwd0_w, fwd0_b, fwd1_w, fwd1_b,
        com0_w, com0_b, com1_w, com1_b,
        bwd0_w, bwd0_b, bwd1_w, bwd1_b,
        cost0_w, cost0_b, cost1_w, cost1_b,
        pol_w, pol_b,
        (float*)d_out, S);
}

// round 6
// speedup vs baseline: 8.2125x; 1.2568x over previous
#include <cuda_runtime.h>
#include <cuda_fp16.h>
#include <cstdint>

// ===========================================================================
// Model_55611236549533 — sm_103a, fp16 mma.m16n8k16 + ldmatrix, 2 CTAs/SM.
//   Per 64-row tile (296 persistent CTAs = 2/SM, 8 warps each):
//     L0: X[64x64]h @ W0[64x256]h (bias in acc, relu) -> H fp16
//     L1: H @ W1[128x32 per branch]h (bias in acc, relu) -> Gs fp16
//     warps 0-3: sorted-run segment reduce (half2) -> atomics
//   W1 B-fragments in registers; W0 B-fragments via in-loop ldmatrix.
// ===========================================================================

#define F_IN   64
#define S_SEG  16384
#define TILE   64
#define BLK    256
#define GRID_A 296

// strides (bytes)
#define LDW0B 144    // W0 [n][k] row stride (72 halves)
#define LDW1B 272    // W1 [n][k] row stride (136 halves)
#define LDXB  144    // X row stride  (72 halves)
#define LDHB  528    // H row stride  (264 halves)
#define LDGB  144    // Gs row stride (72 halves)

// smem byte offsets (16B aligned)
#define O_W0   0                 // 256*144 = 36864
#define O_W1   36864             // 64*272  = 17408
#define O_X    54272             // 64*144  =  9216
#define O_H    63488             // 64*528  = 33792
#define O_GS   97280             // 64*144  =  9216
#define O_B0   106496            // 256 f32 =  1024
#define O_B1   107520            // 64 f32  =   256
#define O_SID  107776            // 128 int =   512
#define SMEM_BYTES 108288

__device__ float g_segbuf[S_SEG * 64];   // [seg][0:32 tfc | 32:64 rl]

// ---------------------------------------------------------------- PTX utils
__device__ __forceinline__ uint32_t smem_u32(const void* p) {
    uint32_t a;
    asm("{ .reg .u64 t; cvta.to.shared.u64 t, %1; cvt.u32.u64 %0, t; }"
        : "=r"(a) : "l"(p));
    return a;
}
__device__ __forceinline__ uint32_t h2u(__half2 h) {
    return *reinterpret_cast<uint32_t*>(&h);
}
__device__ __forceinline__ void ldmx4(uint32_t* r, uint32_t addr) {
    asm volatile("ldmatrix.sync.aligned.m8n8.x4.shared.b16 {%0,%1,%2,%3}, [%4];"
                 : "=r"(r[0]), "=r"(r[1]), "=r"(r[2]), "=r"(r[3]) : "r"(addr));
}
__device__ __forceinline__ void ldmx2(uint32_t* r, uint32_t addr) {
    asm volatile("ldmatrix.sync.aligned.m8n8.x2.shared.b16 {%0,%1}, [%2];"
                 : "=r"(r[0]), "=r"(r[1]) : "r"(addr));
}
__device__ __forceinline__ void mma_f16(float* d, const uint32_t* a,
                                        const uint32_t* b) {
    asm volatile(
        "mma.sync.aligned.m16n8k16.row.col.f32.f16.f16.f32 "
        "{%0,%1,%2,%3}, {%4,%5,%6,%7}, {%8,%9}, {%0,%1,%2,%3};"
        : "+f"(d[0]), "+f"(d[1]), "+f"(d[2]), "+f"(d[3])
        : "r"(a[0]), "r"(a[1]), "r"(a[2]), "r"(a[3]), "r"(b[0]), "r"(b[1]));
}

// ------------------------------------------------------------ zero segbuf
__global__ void zero_kernel(int n4) {
    int i = blockIdx.x * blockDim.x + threadIdx.x;
    if (i < n4)
        reinterpret_cast<float4*>(g_segbuf)[i] = make_float4(0.f, 0.f, 0.f, 0.f);
}

// -------------------------------------------------------------- phase A
__global__ __launch_bounds__(BLK, 2)
void phaseA_mma(const float* __restrict__ x,
                const int*   __restrict__ seg_ids,
                const float* __restrict__ tfc0_w, const float* __restrict__ tfc0_b,
                const float* __restrict__ tfc1_w, const float* __restrict__ tfc1_b,
                const float* __restrict__ rl0_w,  const float* __restrict__ rl0_b,
                const float* __restrict__ rl1_w,  const float* __restrict__ rl1_b,
                int N)
{
    extern __shared__ char smc[];
    __half* W0s = (__half*)(smc + O_W0);
    __half* W1s = (__half*)(smc + O_W1);
    __half* Hs  = (__half*)(smc + O_H);
    float*  B0s = (float*)(smc + O_B0);
    float*  B1s = (float*)(smc + O_B1);
    int*    sid_s = (int*)(smc + O_SID);
    const uint32_t smb = smem_u32(smc);

    const int tid  = threadIdx.x;
    const int wid  = tid >> 5;
    const int lane = tid & 31;
    const int lg   = lane >> 2;       // d-frag row
    const int lt   = lane & 3;        // d-frag col pair

    // ---- stage weights ([n][k] fp16) + biases ----
    for (int i = tid; i < 64 * 128; i += BLK) {
        int k = i >> 7, n = i & 127;
        W0s[n * 72 + k]         = __float2half_rn(tfc0_w[i]);
        W0s[(n + 128) * 72 + k] = __float2half_rn(rl0_w[i]);
    }
    for (int i = tid; i < 128 * 32; i += BLK) {
        int k = i >> 5, n = i & 31;
        W1s[n * 136 + k]        = __float2half_rn(tfc1_w[i]);
        W1s[(32 + n) * 136 + k] = __float2half_rn(rl1_w[i]);
    }
    if (tid < 128) { B0s[tid] = tfc0_b[tid]; B0s[128 + tid] = rl0_b[tid]; }
    if (tid < 32)  { B1s[tid] = tfc1_b[tid]; B1s[32 + tid] = rl1_b[tid]; }

    const int ntiles = (N + TILE - 1) / TILE;

    // ---- stage first X tile + sids ----
    int tile = blockIdx.x;
    {
        int r = tid >> 2, q = (tid & 3) * 16;
        long g = (long)tile * TILE + r;
        bool ok = (tile < ntiles) && (g < N);
        float4 v0 = make_float4(0.f,0.f,0.f,0.f), v1 = v0, v2 = v0, v3 = v0;
        if (ok) {
            const float4* xp = reinterpret_cast<const float4*>(&x[g * F_IN + q]);
            v0 = xp[0]; v1 = xp[1]; v2 = xp[2]; v3 = xp[3];
        }
        uint32_t h0 = h2u(__floats2half2_rn(v0.x, v0.y));
        uint32_t h1 = h2u(__floats2half2_rn(v0.z, v0.w));
        uint32_t h2 = h2u(__floats2half2_rn(v1.x, v1.y));
        uint32_t h3 = h2u(__floats2half2_rn(v1.z, v1.w));
        uint32_t h4 = h2u(__floats2half2_rn(v2.x, v2.y));
        uint32_t h5 = h2u(__floats2half2_rn(v2.z, v2.w));
        uint32_t h6 = h2u(__floats2half2_rn(v3.x, v3.y));
        uint32_t h7 = h2u(__floats2half2_rn(v3.z, v3.w));
        uint32_t base = smb + O_X + r * LDXB + q * 2;
        asm volatile("st.shared.v4.b32 [%0], {%1,%2,%3,%4};" ::
            "r"(base), "r"(h0), "r"(h1), "r"(h2), "r"(h3));
        asm volatile("st.shared.v4.b32 [%0], {%1,%2,%3,%4};" ::
            "r"(base + 16), "r"(h4), "r"(h5), "r"(h6), "r"(h7));
        if (tid < TILE) {
            long gi = (long)tile * TILE + tid;
            sid_s[tid] = (tile < ntiles && gi < N) ? seg_ids[gi] : -1;
        }
    }
    __syncthreads();

    // ---- warp roles ----
    const int mh0 = wid & 1;          // L0 row half
    const int no  = wid >> 1;         // L0 col octet (64 cols)
    const int br  = wid >> 2;         // L1 branch
    const int mh1 = wid & 1;          // L1 row half
    const int nq  = (wid >> 1) & 1;   // L1 col quarter (16 cols)

    // ---- preload W1 B-fragments (32 regs) ----
    uint32_t bw1[2][8][2];
    #pragma unroll
    for (int jn = 0; jn < 2; ++jn)
        #pragma unroll
        for (int kk = 0; kk < 8; ++kk) {
            int n = br * 32 + nq * 16 + jn * 8 + (lane & 7);
            int k = kk * 16 + ((lane >> 3) & 1) * 8;
            ldmx2(bw1[jn][kk], smb + O_W1 + n * LDW1B + k * 2);
        }

    int p = 0;
    for (; tile < ntiles; tile += GRID_A) {
        const int valid = min(TILE, N - tile * TILE);
        const int ntile = tile + GRID_A;

        // ---- prefetch next tile ----
        float4 px[4];
        int    psid = -1;
        {
            int r = tid >> 2, q = (tid & 3) * 16;
            long g = (long)ntile * TILE + r;
            bool ok = (ntile < ntiles) && (g < N);
            #pragma unroll
            for (int i = 0; i < 4; ++i) {
                px[i] = make_float4(0.f, 0.f, 0.f, 0.f);
                if (ok) px[i] = *reinterpret_cast<const float4*>(
                            &x[g * F_IN + q + i * 4]);
            }
            long gi = (long)ntile * TILE + tid;
            if (tid < TILE && ntile < ntiles && gi < N) psid = seg_ids[gi];
        }

        // =============== Layer 0 (two 32-col halves) ===============
        #pragma unroll
        for (int nh = 0; nh < 2; ++nh) {
            const int cb = no * 64 + nh * 32;
            float acc[2][4][4];
            #pragma unroll
            for (int j = 0; j < 4; ++j) {
                float2 bv = *reinterpret_cast<const float2*>(&B0s[cb + j * 8 + 2 * lt]);
                #pragma unroll
                for (int m = 0; m < 2; ++m) {
                    acc[m][j][0] = bv.x; acc[m][j][1] = bv.y;
                    acc[m][j][2] = bv.x; acc[m][j][3] = bv.y;
                }
            }
            #pragma unroll
            for (int k2 = 0; k2 < 4; ++k2) {
                uint32_t a[2][4];
                #pragma unroll
                for (int m = 0; m < 2; ++m) {
                    int row = mh0 * 32 + m * 16 + (lane & 15);
                    int kc  = k2 * 16 + ((lane >> 4) << 3);
                    ldmx4(a[m], smb + O_X + row * LDXB + kc * 2);
                }
                #pragma unroll
                for (int j = 0; j < 4; ++j) {
                    uint32_t b[2];
                    int n = cb + j * 8 + (lane & 7);
                    int k = k2 * 16 + ((lane >> 3) & 1) * 8;
                    ldmx2(b, smb + O_W0 + n * LDW0B + k * 2);
                    mma_f16(acc[0][j], a[0], b);
                    mma_f16(acc[1][j], a[1], b);
                }
            }
            // relu + pack -> H fp16
            const __half2 z2 = __float2half2_rn(0.f);
            #pragma unroll
            for (int j = 0; j < 4; ++j) {
                int col = cb + j * 8 + 2 * lt;
                #pragma unroll
                for (int m = 0; m < 2; ++m) {
                    int row = mh0 * 32 + m * 16 + lg;
                    __half2 lo = __hmax2(__floats2half2_rn(acc[m][j][0], acc[m][j][1]), z2);
                    __half2 hi = __hmax2(__floats2half2_rn(acc[m][j][2], acc[m][j][3]), z2);
                    *reinterpret_cast<__half2*>((char*)Hs + row * LDHB + col * 2) = lo;
                    *reinterpret_cast<__half2*>((char*)Hs + (row + 8) * LDHB + col * 2) = hi;
                }
            }
        }
        __syncthreads();

        // ---- store prefetched X + sid (Xs free after L0) ----
        {
            int r = tid >> 2, q = (tid & 3) * 16;
            uint32_t h0 = h2u(__floats2half2_rn(px[0].x, px[0].y));
            uint32_t h1 = h2u(__floats2half2_rn(px[0].z, px[0].w));
            uint32_t h2 = h2u(__floats2half2_rn(px[1].x, px[1].y));
            uint32_t h3 = h2u(__floats2half2_rn(px[1].z, px[1].w));
            uint32_t h4 = h2u(__floats2half2_rn(px[2].x, px[2].y));
            uint32_t h5 = h2u(__floats2half2_rn(px[2].z, px[2].w));
            uint32_t h6 = h2u(__floats2half2_rn(px[3].x, px[3].y));
            uint32_t h7 = h2u(__floats2half2_rn(px[3].z, px[3].w));
            uint32_t base = smb + O_X + r * LDXB + q * 2;
            asm volatile("st.shared.v4.b32 [%0], {%1,%2,%3,%4};" ::
                "r"(base), "r"(h0), "r"(h1), "r"(h2), "r"(h3));
            asm volatile("st.shared.v4.b32 [%0], {%1,%2,%3,%4};" ::
                "r"(base + 16), "r"(h4), "r"(h5), "r"(h6), "r"(h7));
            if (tid < TILE) sid_s[(p ^ 1) * TILE + tid] = psid;
        }

        // =============== Layer 1 ===============
        {
            float acc[2][2][4];
            #pragma unroll
            for (int jn = 0; jn < 2; ++jn) {
                int col = br * 32 + nq * 16 + jn * 8 + 2 * lt;
                float2 bv = *reinterpret_cast<const float2*>(&B1s[col]);
                #pragma unroll
                for (int m = 0; m < 2; ++m) {
                    acc[m][jn][0] = bv.x; acc[m][jn][1] = bv.y;
                    acc[m][jn][2] = bv.x; acc[m][jn][3] = bv.y;
                }
            }
            #pragma unroll
            for (int kk = 0; kk < 8; ++kk) {
                uint32_t a[2][4];
                #pragma unroll
                for (int m = 0; m < 2; ++m) {
                    int row = mh1 * 32 + m * 16 + (lane & 15);
                    int kc  = br * 128 + kk * 16 + ((lane >> 4) << 3);
                    ldmx4(a[m], smb + O_H + row * LDHB + kc * 2);
                }
                #pragma unroll
                for (int jn = 0; jn < 2; ++jn) {
                    mma_f16(acc[0][jn], a[0], bw1[jn][kk]);
                    mma_f16(acc[1][jn], a[1], bw1[jn][kk]);
                }
            }
            // relu + pack -> Gs fp16
            const __half2 z2 = __float2half2_rn(0.f);
            #pragma unroll
            for (int jn = 0; jn < 2; ++jn) {
                int col = br * 32 + nq * 16 + jn * 8 + 2 * lt;
                #pragma unroll
                for (int m = 0; m < 2; ++m) {
                    int row = mh1 * 32 + m * 16 + lg;
                    __half2 lo = __hmax2(__floats2half2_rn(acc[m][jn][0], acc[m][jn][1]), z2);
                    __half2 hi = __hmax2(__floats2half2_rn(acc[m][jn][2], acc[m][jn][3]), z2);
                    *reinterpret_cast<__half2*>(smc + O_GS + row * LDGB + col * 2) = lo;
                    *reinterpret_cast<__half2*>(smc + O_GS + (row + 8) * LDGB + col * 2) = hi;
                }
            }
        }
        __syncthreads();

        // ---- sorted-run segment reduction (warps 0-3; half2 cols) ----
        if (tid < 128) {
            const int cp    = tid & 31;          // col pair (2 cols)
            const int chunk = tid >> 5;          // 4 chunks x 16 rows
            const int rbeg = chunk * 16;
            const int rend = min(rbeg + 16, valid);
            const int* sid = &sid_s[p * TILE];
            if (rbeg < rend) {
                int prev = sid[rbeg];
                float rx = 0.f, ry = 0.f;
                for (int r = rbeg; r < rend; ++r) {
                    int sd = sid[r];
                    if (sd != prev) {
                        atomicAdd(&g_segbuf[prev * 64 + 2 * cp], rx);
                        atomicAdd(&g_segbuf[prev * 64 + 2 * cp + 1], ry);
                        rx = 0.f; ry = 0.f; prev = sd;
                    }
                    __half2 h = *reinterpret_cast<const __half2*>(
                        smc + O_GS + r * LDGB + cp * 4);
                    float2 f = __half22float2(h);
                    rx += f.x; ry += f.y;
                }
                atomicAdd(&g_segbuf[prev * 64 + 2 * cp], rx);
                atomicAdd(&g_segbuf[prev * 64 + 2 * cp + 1], ry);
            }
        }
        p ^= 1;
        // warps 4-7 run ahead into next L0 (no Gs/Hs hazard: L1 readers all
        // passed the pre-reduction barrier; next Gs writes gated by next
        // post-L0 barrier).
    }
}

// ---------------------------------------------------------------- phase B
__global__ __launch_bounds__(256)
void phaseB_kernel(const float* __restrict__ fwd0_w, const float* __restrict__ fwd0_b,
                   const float* __restrict__ fwd1_w, const float* __restrict__ fwd1_b,
                   const float* __restrict__ com0_w, const float* __restrict__ com0_b,
                   const float* __restrict__ com1_w, const float* __restrict__ com1_b,
                   const float* __restrict__ bwd0_w, const float* __restrict__ bwd0_b,
                   const float* __restrict__ bwd1_w, const float* __restrict__ bwd1_b,
                   const float* __restrict__ cost0_w, const float* __restrict__ cost0_b,
                   const float* __restrict__ cost1_w, const float* __restrict__ cost1_b,
                   const float* __restrict__ pol_w,   const float* __restrict__ pol_b,
                   float* __restrict__ out, int S)
{
    __shared__ float s_f0[32 * 64], s_c0[32 * 64], s_b0[32 * 64];
    __shared__ float s_f0b[64], s_c0b[64], s_b0b[64];
    __shared__ float s_f1[64], s_c1[64], s_b1[64];
    __shared__ float s_k0[3 * 64], s_k0b[64];
    __shared__ float s_k1[64 * 32], s_k1b[32];
    __shared__ float s_pol[64];
    __shared__ float s_scal[4];

    const int t = threadIdx.x;
    for (int i = t; i < 32 * 64; i += 256) {
        s_f0[i] = fwd0_w[i]; s_c0[i] = com0_w[i]; s_b0[i] = bwd0_w[i];
    }
    for (int i = t; i < 64 * 32; i += 256) s_k1[i] = cost1_w[i];
    if (t < 64) {
        s_f0b[t] = fwd0_b[t]; s_c0b[t] = com0_b[t]; s_b0b[t] = bwd0_b[t];
        s_f1[t] = fwd1_w[t];  s_c1[t] = com1_w[t];  s_b1[t] = bwd1_w[t];
        s_k0b[t] = cost0_b[t]; s_pol[t] = pol_w[t];
    }
    if (t < 3 * 64) s_k0[t] = cost0_w[t];
    if (t < 32) s_k1b[t] = cost1_b[t];
    if (t == 0) {
        s_scal[0] = fwd1_b[0]; s_scal[1] = com1_b[0];
        s_scal[2] = bwd1_b[0]; s_scal[3] = pol_b[0];
    }
    __syncthreads();

    const int l = t & 31;
    const int warp = (blockIdx.x * blockDim.x + t) >> 5;
    const int nwarps = (gridDim.x * blockDim.x) >> 5;

    for (int s = warp; s < S; s += nwarps) {
        const float st = g_segbuf[s * 64 + l];
        const float sr = g_segbuf[s * 64 + 32 + l];

        float hf0 = s_f0b[l], hf1 = s_f0b[l + 32];
        float hc0 = s_c0b[l], hc1 = s_c0b[l + 32];
        float hb0 = s_b0b[l], hb1 = s_b0b[l + 32];
        #pragma unroll
        for (int k = 0; k < 32; ++k) {
            float sk = __shfl_sync(0xffffffffu, st, k);
            hf0 = fmaf(sk, s_f0[k * 64 + l],      hf0);
            hf1 = fmaf(sk, s_f0[k * 64 + l + 32], hf1);
            hc0 = fmaf(sk, s_c0[k * 64 + l],      hc0);
            hc1 = fmaf(sk, s_c0[k * 64 + l + 32], hc1);
            hb0 = fmaf(sk, s_b0[k * 64 + l],      hb0);
            hb1 = fmaf(sk, s_b0[k * 64 + l + 32], hb1);
        }
        float vf = fmaxf(hf0, 0.f) * s_f1[l] + fmaxf(hf1, 0.f) * s_f1[l + 32];
        float vc = fmaxf(hc0, 0.f) * s_c1[l] + fmaxf(hc1, 0.f) * s_c1[l + 32];
        float vb = fmaxf(hb0, 0.f) * s_b1[l] + fmaxf(hb1, 0.f) * s_b1[l + 32];
        #pragma unroll
        for (int o = 16; o > 0; o >>= 1) {
            vf += __shfl_xor_sync(0xffffffffu, vf, o);
            vc += __shfl_xor_sync(0xffffffffu, vc, o);
            vb += __shfl_xor_sync(0xffffffffu, vb, o);
        }
        const float fwd = vf + s_scal[0];
        const float com = vc + s_scal[1];
        const float bwd = vb + s_scal[2];

        float c1a = fmaf(fwd, s_k0[l],
                    fmaf(com, s_k0[64 + l],
                    fmaf(bwd, s_k0[128 + l], s_k0b[l])));
        float c1b = fmaf(fwd, s_k0[l + 32],
                    fmaf(com, s_k0[64 + l + 32],
                    fmaf(bwd, s_k0[128 + l + 32], s_k0b[l + 32])));
        c1a = fmaxf(c1a, 0.f);
        c1b = fmaxf(c1b, 0.f);

        float c2 = s_k1b[l];
        #pragma unroll
        for (int jj = 0; jj < 32; ++jj) {
            float a = __shfl_sync(0xffffffffu, c1a, jj);
            float b = __shfl_sync(0xffffffffu, c1b, jj);
            c2 = fmaf(a, s_k1[jj * 32 + l], c2);
            c2 = fmaf(b, s_k1[(jj + 32) * 32 + l], c2);
        }
        c2 = fmaxf(c2, 0.f);

        float v = fmaf(sr, s_pol[l], c2 * s_pol[l + 32]);
        #pragma unroll
        for (int o = 16; o > 0; o >>= 1)
            v += __shfl_xor_sync(0xffffffffu, v, o);
        if (l == 0) out[s] = v + s_scal[3];
    }
}

// ----------------------------------------------------------------- launch
extern "C" void kernel_launch(void* const* d_in, const int* in_sizes, int n_in,
                              void* d_out, int out_size)
{
    const float* x      = (const float*)d_in[0];
    const int*   sid    = (const int*)  d_in[1];
    const float* tfc0_w = (const float*)d_in[4];
    const float* tfc0_b = (const float*)d_in[5];
    const float* tfc1_w = (const float*)d_in[6];
    const float* tfc1_b = (const float*)d_in[7];
    const float* fwd0_w = (const float*)d_in[8];
    const float* fwd0_b = (const float*)d_in[9];
    const float* fwd1_w = (const float*)d_in[10];
    const float* fwd1_b = (const float*)d_in[11];
    const float* com0_w = (const float*)d_in[12];
    const float* com0_b = (const float*)d_in[13];
    const float* com1_w = (const float*)d_in[14];
    const float* com1_b = (const float*)d_in[15];
    const float* bwd0_w = (const float*)d_in[16];
    const float* bwd0_b = (const float*)d_in[17];
    const float* bwd1_w = (const float*)d_in[18];
    const float* bwd1_b = (const float*)d_in[19];
    const float* rl0_w  = (const float*)d_in[20];
    const float* rl0_b  = (const float*)d_in[21];
    const float* rl1_w  = (const float*)d_in[22];
    const float* rl1_b  = (const float*)d_in[23];
    const float* cost0_w = (const float*)d_in[24];
    const float* cost0_b = (const float*)d_in[25];
    const float* cost1_w = (const float*)d_in[26];
    const float* cost1_b = (const float*)d_in[27];
    const float* pol_w   = (const float*)d_in[28];
    const float* pol_b   = (const float*)d_in[29];

    const int N = in_sizes[0] / F_IN;
    const int S = out_size;

    static int configured = 0;
    if (!configured) {
        cudaFuncSetAttribute(phaseA_mma,
                             cudaFuncAttributeMaxDynamicSharedMemorySize,
                             SMEM_BYTES);
        configured = 1;
    }

    {
        int n4 = (S_SEG * 64) / 4;
        zero_kernel<<<(n4 + 255) / 256, 256>>>(n4);
    }

    phaseA_mma<<<GRID_A, BLK, SMEM_BYTES>>>(
        x, sid, tfc0_w, tfc0_b, tfc1_w, tfc1_b,
        rl0_w, rl0_b, rl1_w, rl1_b, N);

    phaseB_kernel<<<128, 256>>>(
        fwd0_w, fwd0_b, fwd1_w, fwd1_b,
        com0_w, com0_b, com1_w, com1_b,
        bwd0_w, bwd0_b, bwd1_w, bwd1_b,
        cost0_w, cost0_b, cost1_w, cost1_b,
        pol_w, pol_b,
        (float*)d_out, S);
}